// round 9
// baseline (speedup 1.0000x reference)
#include <cuda_runtime.h>
#include <cuda_fp16.h>
#include <math.h>
#include <stdint.h>

#define SEQ    2048
#define BATCH  2
#define DIM    1024
#define HEADS  16
#define DH     64
#define MROWS  (BATCH*SEQ)          // 4096
#define QKVCOL (3*DIM)              // 3072

__device__ float g_qkv [MROWS * QKVCOL];
__device__ float g_attn[MROWS * DIM];

// ---------------------------------------------------------------------------
__device__ __forceinline__ uint32_t smem_u32(const void* p){
    return (uint32_t)__cvta_generic_to_shared(p);
}
__device__ __forceinline__ uint32_t pkh(float lo, float hi){
    __half2 h = __floats2half2_rn(lo, hi);
    return *reinterpret_cast<uint32_t*>(&h);
}
__device__ __forceinline__ void mma16(float* c, const uint32_t* a, const uint32_t* b){
    asm volatile("mma.sync.aligned.m16n8k16.row.col.f32.f16.f16.f32 "
        "{%0,%1,%2,%3}, {%4,%5,%6,%7}, {%8,%9}, {%0,%1,%2,%3};"
        : "+f"(c[0]),"+f"(c[1]),"+f"(c[2]),"+f"(c[3])
        : "r"(a[0]),"r"(a[1]),"r"(a[2]),"r"(a[3]),"r"(b[0]),"r"(b[1]));
}
__device__ __forceinline__ void ldsm4(uint32_t& r0, uint32_t& r1, uint32_t& r2, uint32_t& r3,
                                      uint32_t addr){
    asm volatile("ldmatrix.sync.aligned.m8n8.x4.shared.b16 {%0,%1,%2,%3}, [%4];"
        : "=r"(r0),"=r"(r1),"=r"(r2),"=r"(r3) : "r"(addr));
}
__device__ __forceinline__ void ldsm4t(uint32_t& r0, uint32_t& r1, uint32_t& r2, uint32_t& r3,
                                       uint32_t addr){
    asm volatile("ldmatrix.sync.aligned.m8n8.x4.trans.shared.b16 {%0,%1,%2,%3}, [%4];"
        : "=r"(r0),"=r"(r1),"=r"(r2),"=r"(r3) : "r"(addr));
}

// ---------------------------------------------------------------------------
// fp16 GEMM: C[M,N] = A[M,K] @ B[N,K]^T (fp32 in/out, fp16 tensor, fp32 acc).
// CTA 128x128, 256 threads (8 warps, 4x2), warp tile 32x64, BK=32, double buf.
// Row stride 40 fp16 = 80B (conflict-free ldmatrix).
// ---------------------------------------------------------------------------
#define GRB 80          // row stride bytes
#define GBUF (128*GRB)  // one buffer

__global__ void __launch_bounds__(256,2) gemm_h(const float* __restrict__ A,
                                                const float* __restrict__ B,
                                                float* __restrict__ C,
                                                int M, int N, int K)
{
    __shared__ __align__(16) unsigned char As[2][GBUF];
    __shared__ __align__(16) unsigned char Bs[2][GBUF];

    const int tid  = threadIdx.x;
    const int lane = tid & 31, wid = tid >> 5;
    const int g = lane >> 2, t = lane & 3;
    const int wm = wid & 3, wn = wid >> 2;
    const int bm = blockIdx.y * 128, bn = blockIdx.x * 128;

    const uint32_t As0 = smem_u32(As), Bs0 = smem_u32(Bs);
    const uint32_t a_lo = (uint32_t)((lane & 15) * GRB + (lane >> 4) * 16);
    const uint32_t b_lo = (uint32_t)(((lane & 7) + ((lane >> 4) & 1) * 8) * GRB + ((lane >> 3) & 1) * 16);

    // fill mapping: thread owns row tid>>1, 16 fp32 at k-offset (tid&1)*16
    const int frow = tid >> 1, fko = (tid & 1) * 16;
    const float* Ag = A + (size_t)(bm + frow) * K + fko;
    const float* Bg = B + (size_t)(bn + frow) * K + fko;
    const uint32_t sA = As0 + (uint32_t)(frow * GRB + fko * 2);
    const uint32_t sB = Bs0 + (uint32_t)(frow * GRB + fko * 2);

    float acc[2][8][4] = {};
    const int NC = K / 32;

    float4 ra[4], rb[4];
    #pragma unroll
    for (int i = 0; i < 4; i++) { ra[i] = ((const float4*)Ag)[i]; rb[i] = ((const float4*)Bg)[i]; }
    #pragma unroll
    for (int i = 0; i < 2; i++) {
        asm volatile("st.shared.v4.b32 [%0], {%1,%2,%3,%4};" :: "r"(sA + i*16),
            "r"(pkh(ra[2*i].x,ra[2*i].y)), "r"(pkh(ra[2*i].z,ra[2*i].w)),
            "r"(pkh(ra[2*i+1].x,ra[2*i+1].y)), "r"(pkh(ra[2*i+1].z,ra[2*i+1].w)));
        asm volatile("st.shared.v4.b32 [%0], {%1,%2,%3,%4};" :: "r"(sB + i*16),
            "r"(pkh(rb[2*i].x,rb[2*i].y)), "r"(pkh(rb[2*i].z,rb[2*i].w)),
            "r"(pkh(rb[2*i+1].x,rb[2*i+1].y)), "r"(pkh(rb[2*i+1].z,rb[2*i+1].w)));
    }
    __syncthreads();

    for (int c = 0; c < NC; c++) {
        const int buf = c & 1;
        const uint32_t abase = As0 + (uint32_t)buf * GBUF + (uint32_t)(wm * 32 * GRB);
        const uint32_t bbase = Bs0 + (uint32_t)buf * GBUF + (uint32_t)(wn * 64 * GRB);

        if (c + 1 < NC) {
            const float* Ag2 = Ag + (c + 1) * 32;
            const float* Bg2 = Bg + (c + 1) * 32;
            #pragma unroll
            for (int i = 0; i < 4; i++) { ra[i] = ((const float4*)Ag2)[i]; rb[i] = ((const float4*)Bg2)[i]; }
        }

        #pragma unroll
        for (int ks = 0; ks < 2; ks++) {
            uint32_t af[2][4], bf[8][2];
            #pragma unroll
            for (int ma = 0; ma < 2; ma++)
                ldsm4(af[ma][0], af[ma][1], af[ma][2], af[ma][3],
                      abase + (uint32_t)(ma * 16 * GRB + ks * 32) + a_lo);
            #pragma unroll
            for (int p = 0; p < 4; p++)
                ldsm4(bf[2*p][0], bf[2*p][1], bf[2*p+1][0], bf[2*p+1][1],
                      bbase + (uint32_t)(p * 16 * GRB + ks * 32) + b_lo);
            #pragma unroll
            for (int ma = 0; ma < 2; ma++)
                #pragma unroll
                for (int nb = 0; nb < 8; nb++)
                    mma16(acc[ma][nb], af[ma], bf[nb]);
        }

        if (c + 1 < NC) {
            const uint32_t dA = sA + (uint32_t)((buf ^ 1) * GBUF);
            const uint32_t dB = sB + (uint32_t)((buf ^ 1) * GBUF);
            #pragma unroll
            for (int i = 0; i < 2; i++) {
                asm volatile("st.shared.v4.b32 [%0], {%1,%2,%3,%4};" :: "r"(dA + i*16),
                    "r"(pkh(ra[2*i].x,ra[2*i].y)), "r"(pkh(ra[2*i].z,ra[2*i].w)),
                    "r"(pkh(ra[2*i+1].x,ra[2*i+1].y)), "r"(pkh(ra[2*i+1].z,ra[2*i+1].w)));
                asm volatile("st.shared.v4.b32 [%0], {%1,%2,%3,%4};" :: "r"(dB + i*16),
                    "r"(pkh(rb[2*i].x,rb[2*i].y)), "r"(pkh(rb[2*i].z,rb[2*i].w)),
                    "r"(pkh(rb[2*i+1].x,rb[2*i+1].y)), "r"(pkh(rb[2*i+1].z,rb[2*i+1].w)));
            }
        }
        __syncthreads();
    }

    #pragma unroll
    for (int ma = 0; ma < 2; ma++) {
        const int r0 = bm + wm*32 + ma*16 + g;
        #pragma unroll
        for (int nb = 0; nb < 8; nb++) {
            const int c0 = bn + wn*64 + nb*8 + 2*t;
            *(float2*)&C[(size_t)r0     * N + c0] = make_float2(acc[ma][nb][0], acc[ma][nb][1]);
            *(float2*)&C[(size_t)(r0+8) * N + c0] = make_float2(acc[ma][nb][2], acc[ma][nb][3]);
        }
    }
}

// ---------------------------------------------------------------------------
// Flash attention, fp16 mma.sync m16n8k16. 256 threads, 8 warps x 16 q-rows.
// K/V tiles of 64 in fp16 smem (stride 72 fp16 = 144B). V via ldmatrix.trans.
// P->A-fragment is a direct pairwise pack of the S accumulator (no shuffles).
// ---------------------------------------------------------------------------
#define ARB 144         // attention row stride bytes (72 fp16)

__global__ void __launch_bounds__(256) attn_h(const float* __restrict__ qkv,
                                              float* __restrict__ outp)
{
    __shared__ __align__(16) __half sh[2*64*72];    // 18432 B; Q staging overlays
    __half* Ks = sh;                                // [64 kv][72]
    __half* Vs = sh + 64*72;                        // [64 kv][72]
    __half* Qs = sh;                                // [128 q][72] staging

    const int tid = threadIdx.x;
    const int lane = tid & 31, wid = tid >> 5;
    const int g = lane >> 2, t = lane & 3;
    const int bh = blockIdx.y, b = bh >> 4, h = bh & 15;
    const int q0 = blockIdx.x * 128;
    const float* base = qkv + (size_t)b * SEQ * QKVCOL;

    const uint32_t Ks0 = smem_u32(Ks), Vs0 = smem_u32(Vs), Qs0 = smem_u32(Qs);
    const uint32_t a_lo = (uint32_t)((lane & 15) * ARB + (lane >> 4) * 16);
    const uint32_t b_lo = (uint32_t)(((lane & 7) + ((lane >> 4) & 1) * 8) * ARB + ((lane >> 3) & 1) * 16);
    const uint32_t v_lo = (uint32_t)(((lane & 7) + ((lane >> 3) & 1) * 8) * ARB + (lane >> 4) * 16);

    // stage Q (scaled by 1/8, fp16) into smem
    {
        const int r = tid >> 1, f0 = (tid & 1) * 32;
        const float* qr = base + (size_t)(q0 + r) * QKVCOL + h*DH + f0;
        uint32_t dst = Qs0 + (uint32_t)(r * ARB + f0 * 2);
        #pragma unroll
        for (int i = 0; i < 4; i++) {
            float4 q0v = ((const float4*)qr)[2*i];
            float4 q1v = ((const float4*)qr)[2*i+1];
            asm volatile("st.shared.v4.b32 [%0], {%1,%2,%3,%4};" :: "r"(dst + i*16),
                "r"(pkh(q0v.x*0.125f,q0v.y*0.125f)), "r"(pkh(q0v.z*0.125f,q0v.w*0.125f)),
                "r"(pkh(q1v.x*0.125f,q1v.y*0.125f)), "r"(pkh(q1v.z*0.125f,q1v.w*0.125f)));
        }
    }
    __syncthreads();

    uint32_t qf[4][4];
    #pragma unroll
    for (int kc = 0; kc < 4; kc++)
        ldsm4(qf[kc][0], qf[kc][1], qf[kc][2], qf[kc][3],
              Qs0 + (uint32_t)(wid * 16 * ARB + kc * 32) + a_lo);
    __syncthreads();

    float o[8][4] = {};
    float m0 = -INFINITY, m1 = -INFINITY, l0 = 0.f, l1 = 0.f;
    const int row0 = q0 + wid*16 + g;
    const int ntiles = q0/64 + 2;

    // fill mapping: row tid&63, 16 dh-floats at offset (tid>>6)*16
    const int fr = tid & 63, fc = (tid >> 6) * 16;
    const float* Kg = base + (size_t)fr * QKVCOL +     DIM + h*DH + fc;
    const float* Vg = base + (size_t)fr * QKVCOL + 2 * DIM + h*DH + fc;
    const size_t tstep = (size_t)64 * QKVCOL;
    const uint32_t kdst = Ks0 + (uint32_t)(fr * ARB + fc * 2);
    const uint32_t vdst = Vs0 + (uint32_t)(fr * ARB + fc * 2);

    float4 rk[4], rv[4];
    #pragma unroll
    for (int i = 0; i < 4; i++) { rk[i] = ((const float4*)Kg)[i]; rv[i] = ((const float4*)Vg)[i]; }

    for (int kt = 0; kt < ntiles; kt++) {
        // commit prefetched K/V tile to smem (fp16)
        #pragma unroll
        for (int i = 0; i < 2; i++) {
            asm volatile("st.shared.v4.b32 [%0], {%1,%2,%3,%4};" :: "r"(kdst + i*16),
                "r"(pkh(rk[2*i].x,rk[2*i].y)), "r"(pkh(rk[2*i].z,rk[2*i].w)),
                "r"(pkh(rk[2*i+1].x,rk[2*i+1].y)), "r"(pkh(rk[2*i+1].z,rk[2*i+1].w)));
            asm volatile("st.shared.v4.b32 [%0], {%1,%2,%3,%4};" :: "r"(vdst + i*16),
                "r"(pkh(rv[2*i].x,rv[2*i].y)), "r"(pkh(rv[2*i].z,rv[2*i].w)),
                "r"(pkh(rv[2*i+1].x,rv[2*i+1].y)), "r"(pkh(rv[2*i+1].z,rv[2*i+1].w)));
        }
        __syncthreads();

        // prefetch next tile (overlaps compute)
        if (kt + 1 < ntiles) {
            const float* Kg2 = Kg + (size_t)(kt + 1) * tstep;
            const float* Vg2 = Vg + (size_t)(kt + 1) * tstep;
            #pragma unroll
            for (int i = 0; i < 4; i++) { rk[i] = ((const float4*)Kg2)[i]; rv[i] = ((const float4*)Vg2)[i]; }
        }

        // ---- S = Q @ K^T ----
        float s[8][4] = {};
        #pragma unroll
        for (int kc = 0; kc < 4; kc++) {
            uint32_t bk[8][2];
            #pragma unroll
            for (int p = 0; p < 4; p++)
                ldsm4(bk[2*p][0], bk[2*p][1], bk[2*p+1][0], bk[2*p+1][1],
                      Ks0 + (uint32_t)(p * 16 * ARB + kc * 32) + b_lo);
            #pragma unroll
            for (int nb = 0; nb < 8; nb++)
                mma16(s[nb], qf[kc], bk[nb]);
        }

        // ---- causal mask + online softmax ----
        const int colbase = kt*64 + 2*t;
        float t0 = -INFINITY, t1 = -INFINITY;
        #pragma unroll
        for (int na = 0; na < 8; na++) {
            const int c = colbase + na*8;
            if (c     > row0)     s[na][0] = -INFINITY;
            if (c + 1 > row0)     s[na][1] = -INFINITY;
            if (c     > row0 + 8) s[na][2] = -INFINITY;
            if (c + 1 > row0 + 8) s[na][3] = -INFINITY;
            t0 = fmaxf(t0, fmaxf(s[na][0], s[na][1]));
            t1 = fmaxf(t1, fmaxf(s[na][2], s[na][3]));
        }
        t0 = fmaxf(t0, __shfl_xor_sync(0xffffffffu, t0, 1));
        t0 = fmaxf(t0, __shfl_xor_sync(0xffffffffu, t0, 2));
        t1 = fmaxf(t1, __shfl_xor_sync(0xffffffffu, t1, 1));
        t1 = fmaxf(t1, __shfl_xor_sync(0xffffffffu, t1, 2));

        const float mn0 = fmaxf(m0, t0), mn1 = fmaxf(m1, t1);
        const float sc0 = __expf(m0 - mn0), sc1 = __expf(m1 - mn1);
        m0 = mn0; m1 = mn1; l0 *= sc0; l1 *= sc1;

        #pragma unroll
        for (int na = 0; na < 8; na++) {
            o[na][0] *= sc0; o[na][1] *= sc0; o[na][2] *= sc1; o[na][3] *= sc1;
            s[na][0] = __expf(s[na][0] - m0);
            s[na][1] = __expf(s[na][1] - m0);
            s[na][2] = __expf(s[na][2] - m1);
            s[na][3] = __expf(s[na][3] - m1);
            l0 += s[na][0] + s[na][1];
            l1 += s[na][2] + s[na][3];
        }

        // ---- O += P @ V (P packs directly into fp16 a-frags; V via ldsm.trans) ----
        #pragma unroll
        for (int kc = 0; kc < 4; kc++) {
            uint32_t pa[4];
            pa[0] = pkh(s[2*kc][0],   s[2*kc][1]);
            pa[1] = pkh(s[2*kc][2],   s[2*kc][3]);
            pa[2] = pkh(s[2*kc+1][0], s[2*kc+1][1]);
            pa[3] = pkh(s[2*kc+1][2], s[2*kc+1][3]);

            uint32_t bv[8][2];
            #pragma unroll
            for (int p = 0; p < 4; p++)
                ldsm4t(bv[2*p][0], bv[2*p][1], bv[2*p+1][0], bv[2*p+1][1],
                       Vs0 + (uint32_t)(kc * 16 * ARB + p * 32) + v_lo);
            #pragma unroll
            for (int nb = 0; nb < 8; nb++)
                mma16(o[nb], pa, bv[nb]);
        }
        __syncthreads();
    }

    l0 += __shfl_xor_sync(0xffffffffu, l0, 1);
    l0 += __shfl_xor_sync(0xffffffffu, l0, 2);
    l1 += __shfl_xor_sync(0xffffffffu, l1, 1);
    l1 += __shfl_xor_sync(0xffffffffu, l1, 2);
    const float i0 = 1.f / l0, i1 = 1.f / l1;

    float* orow0 = outp + (size_t)(b*SEQ + row0) * DIM + h*DH;
    float* orow1 = orow0 + 8*DIM;
    #pragma unroll
    for (int na = 0; na < 8; na++) {
        *(float2*)&orow0[na*8 + 2*t] = make_float2(o[na][0]*i0, o[na][1]*i0);
        *(float2*)&orow1[na*8 + 2*t] = make_float2(o[na][2]*i1, o[na][3]*i1);
    }
}

// ---------------------------------------------------------------------------
extern "C" void kernel_launch(void* const* d_in, const int* in_sizes, int n_in,
                              void* d_out, int out_size)
{
    const float* x     = (const float*)d_in[0];
    const float* W_qkv = (const float*)d_in[1];
    const float* W_out = (const float*)d_in[2];
    float*       out   = (float*)d_out;

    float* qkv  = nullptr;
    float* attn = nullptr;
    cudaGetSymbolAddress((void**)&qkv,  g_qkv);
    cudaGetSymbolAddress((void**)&attn, g_attn);

    // 1) qkv = x @ W_qkv^T
    gemm_h<<<dim3(QKVCOL/128, MROWS/128), 256>>>(x, W_qkv, qkv, MROWS, QKVCOL, DIM);
    // 2) causal attention
    attn_h<<<dim3(SEQ/128, BATCH*HEADS), 256>>>(qkv, attn);
    // 3) out = attn @ W_out^T
    gemm_h<<<dim3(DIM/128, MROWS/128), 256>>>(attn, W_out, out, MROWS, DIM, DIM);
}